// round 1
// baseline (speedup 1.0000x reference)
#include <cuda_runtime.h>
#include <math.h>

// Problem constants
#define BSZ  4
#define SEQ  2048
#define DIM  1024
#define MTOT (BSZ*SEQ)   // 8192 total rows

// GEMM tiling: 128x128 block, BK=8, 8x8 per-thread microtile, 256 threads
#define BM 128
#define BN 128
#define BK 8
#define TM 8
#define TN 8
#define NTHR 256

// Scratch (static device memory; allocation inside kernel_launch is forbidden)
__device__ float g_q[(size_t)MTOT*DIM];
__device__ float g_k[(size_t)MTOT*DIM];
__device__ float g_v[(size_t)MTOT*DIM];
__device__ float g_scores[(size_t)BSZ*SEQ*SEQ];
__device__ float g_attn[(size_t)MTOT*DIM];
__device__ float g_h[(size_t)MTOT*DIM];

// ---------------------------------------------------------------------------
// Tile loaders / compute helpers
// ---------------------------------------------------------------------------

// Load A tile [BM x BK] from row-major A (lda = row stride), store transposed As[k][m]
__device__ __forceinline__ void load_tile_A(const float* __restrict__ A, int lda,
                                            int m0, int k0, int tid,
                                            float (*As)[BM]) {
    int r = tid >> 1;            // 0..127 (row within tile)
    int c = (tid & 1) * 4;       // 0 or 4 (k offset)
    const float4 v = *reinterpret_cast<const float4*>(A + (long)(m0 + r) * lda + k0 + c);
    As[c + 0][r] = v.x;
    As[c + 1][r] = v.y;
    As[c + 2][r] = v.z;
    As[c + 3][r] = v.w;
}

// Load B tile [BK x BN] from row-major B[K,N] (NN case)
__device__ __forceinline__ void load_tile_B_nn(const float* __restrict__ B, int ldb,
                                               int k0, int n0, int tid,
                                               float (*Bs)[BN]) {
    int r = tid >> 5;            // 0..7 (k within tile)
    int c = (tid & 31) * 4;      // 0..124 (n within tile)
    *reinterpret_cast<float4*>(&Bs[r][c]) =
        *reinterpret_cast<const float4*>(B + (long)(k0 + r) * ldb + n0 + c);
}

// Load B tile for C = A * B^T where B is row-major [N,K] (NT case)
__device__ __forceinline__ void load_tile_B_nt(const float* __restrict__ B, int ldb,
                                               int k0, int n0, int tid,
                                               float (*Bs)[BN]) {
    int r = tid >> 1;            // 0..127 (n within tile)
    int c = (tid & 1) * 4;       // 0 or 4 (k offset)
    const float4 v = *reinterpret_cast<const float4*>(B + (long)(n0 + r) * ldb + k0 + c);
    Bs[c + 0][r] = v.x;
    Bs[c + 1][r] = v.y;
    Bs[c + 2][r] = v.z;
    Bs[c + 3][r] = v.w;
}

__device__ __forceinline__ void mma_tile(const float (*As)[BM], const float (*Bs)[BN],
                                         int tid, float acc[TM][TN]) {
    int ty = tid >> 4;
    int tx = tid & 15;
#pragma unroll
    for (int kk = 0; kk < BK; kk++) {
        float4 a0 = *reinterpret_cast<const float4*>(&As[kk][ty * TM]);
        float4 a1 = *reinterpret_cast<const float4*>(&As[kk][ty * TM + 4]);
        float4 b0 = *reinterpret_cast<const float4*>(&Bs[kk][tx * TN]);
        float4 b1 = *reinterpret_cast<const float4*>(&Bs[kk][tx * TN + 4]);
        float ra[8] = {a0.x, a0.y, a0.z, a0.w, a1.x, a1.y, a1.z, a1.w};
        float rb[8] = {b0.x, b0.y, b0.z, b0.w, b1.x, b1.y, b1.z, b1.w};
#pragma unroll
        for (int i = 0; i < TM; i++)
#pragma unroll
            for (int j = 0; j < TN; j++)
                acc[i][j] = fmaf(ra[i], rb[j], acc[i][j]);
    }
}

__device__ __forceinline__ void store_tile(float* __restrict__ C, int ldc,
                                           int m0, int n0, int tid,
                                           float acc[TM][TN], float scale,
                                           const float* __restrict__ bias, bool relu) {
    int ty = tid >> 4;
    int tx = tid & 15;
#pragma unroll
    for (int i = 0; i < TM; i++) {
        long row = m0 + ty * TM + i;
#pragma unroll
        for (int j = 0; j < TN; j += 4) {
            int col = n0 + tx * TN + j;
            float4 v;
            v.x = acc[i][j + 0] * scale;
            v.y = acc[i][j + 1] * scale;
            v.z = acc[i][j + 2] * scale;
            v.w = acc[i][j + 3] * scale;
            if (bias) {
                v.x += bias[col + 0];
                v.y += bias[col + 1];
                v.z += bias[col + 2];
                v.w += bias[col + 3];
            }
            if (relu) {
                v.x = fmaxf(v.x, 0.f);
                v.y = fmaxf(v.y, 0.f);
                v.z = fmaxf(v.z, 0.f);
                v.w = fmaxf(v.w, 0.f);
            }
            *reinterpret_cast<float4*>(&C[row * ldc + col]) = v;
        }
    }
}

// ---------------------------------------------------------------------------
// Kernels
// ---------------------------------------------------------------------------

// q/k/v = x @ W{q,k,v}   (z selects projection)  M=8192, N=K=1024
__global__ __launch_bounds__(NTHR) void k_qkv(const float* __restrict__ x,
                                              const float* __restrict__ Wq,
                                              const float* __restrict__ Wk,
                                              const float* __restrict__ Wv) {
    __shared__ __align__(16) float As[BK][BM];
    __shared__ __align__(16) float Bs[BK][BN];
    const float* B = (blockIdx.z == 0) ? Wq : (blockIdx.z == 1) ? Wk : Wv;
    float* C = (blockIdx.z == 0) ? g_q : (blockIdx.z == 1) ? g_k : g_v;
    int m0 = blockIdx.y * BM, n0 = blockIdx.x * BN, tid = threadIdx.x;
    float acc[TM][TN] = {};
    for (int k0 = 0; k0 < DIM; k0 += BK) {
        load_tile_A(x, DIM, m0, k0, tid, As);
        load_tile_B_nn(B, DIM, k0, n0, tid, Bs);
        __syncthreads();
        mma_tile(As, Bs, tid, acc);
        __syncthreads();
    }
    store_tile(C, DIM, m0, n0, tid, acc, 1.0f, nullptr, false);
}

// scores = (q @ k^T) * scale, per batch; lower-triangular blocks only
__global__ __launch_bounds__(NTHR) void k_scores() {
    int m0 = blockIdx.y * BM, n0 = blockIdx.x * BN;
    if (n0 > m0 + BM - 1) return;  // block fully above the causal diagonal
    int b = blockIdx.z;
    const float* A = g_q + (long)b * SEQ * DIM;
    const float* Bp = g_k + (long)b * SEQ * DIM;
    float* C = g_scores + (long)b * SEQ * SEQ;
    __shared__ __align__(16) float As[BK][BM];
    __shared__ __align__(16) float Bs[BK][BN];
    int tid = threadIdx.x;
    float acc[TM][TN] = {};
    for (int k0 = 0; k0 < DIM; k0 += BK) {
        load_tile_A(A, DIM, m0, k0, tid, As);
        load_tile_B_nt(Bp, DIM, k0, n0, tid, Bs);
        __syncthreads();
        mma_tile(As, Bs, tid, acc);
        __syncthreads();
    }
    store_tile(C, SEQ, m0, n0, tid, acc, 0.03125f, nullptr, false);  // 1/sqrt(1024)
}

// Causal row softmax, in place. One block per row. Writes 0 for masked cols.
__global__ __launch_bounds__(NTHR) void k_softmax() {
    float* p = g_scores + (long)blockIdx.x * SEQ;
    int i = blockIdx.x & (SEQ - 1);   // row within batch
    int cnt = i + 1;                  // valid columns
    int tid = threadIdx.x;
    __shared__ float red[NTHR];

    float vals[SEQ / NTHR];           // 8 elements per thread
    float m = -3.4e38f;
#pragma unroll
    for (int t = 0; t < SEQ / NTHR; t++) {
        int j = t * NTHR + tid;
        vals[t] = (j < cnt) ? p[j] : -3.4e38f;
        m = fmaxf(m, vals[t]);
    }
    red[tid] = m;
    __syncthreads();
    for (int s = NTHR / 2; s > 0; s >>= 1) {
        if (tid < s) red[tid] = fmaxf(red[tid], red[tid + s]);
        __syncthreads();
    }
    m = red[0];
    __syncthreads();

    float sum = 0.f;
#pragma unroll
    for (int t = 0; t < SEQ / NTHR; t++) {
        int j = t * NTHR + tid;
        if (j < cnt) {
            vals[t] = __expf(vals[t] - m);
            sum += vals[t];
        }
    }
    red[tid] = sum;
    __syncthreads();
    for (int s = NTHR / 2; s > 0; s >>= 1) {
        if (tid < s) red[tid] += red[tid + s];
        __syncthreads();
    }
    float inv = 1.0f / red[0];

#pragma unroll
    for (int t = 0; t < SEQ / NTHR; t++) {
        int j = t * NTHR + tid;
        p[j] = (j < cnt) ? vals[t] * inv : 0.f;
    }
}

// attn_out = attn @ v, per batch, K limited to m0+BM (rows above are all-zero attn)
__global__ __launch_bounds__(NTHR) void k_av() {
    int m0 = blockIdx.y * BM, n0 = blockIdx.x * BN;
    int b = blockIdx.z;
    const float* A = g_scores + (long)b * SEQ * SEQ;
    const float* Bp = g_v + (long)b * SEQ * DIM;
    float* C = g_attn + (long)b * SEQ * DIM;
    __shared__ __align__(16) float As[BK][BM];
    __shared__ __align__(16) float Bs[BK][BN];
    int tid = threadIdx.x;
    float acc[TM][TN] = {};
    int kEnd = m0 + BM;  // causal: attn[row, k] == 0 for k > row
    for (int k0 = 0; k0 < kEnd; k0 += BK) {
        load_tile_A(A, SEQ, m0, k0, tid, As);
        load_tile_B_nn(Bp, DIM, k0, n0, tid, Bs);
        __syncthreads();
        mma_tile(As, Bs, tid, acc);
        __syncthreads();
    }
    store_tile(C, DIM, m0, n0, tid, acc, 1.0f, nullptr, false);
}

// h = relu(attn_out @ W1[:1024] + x @ W1[1024:] + b1)
__global__ __launch_bounds__(NTHR) void k_mlp1(const float* __restrict__ x,
                                               const float* __restrict__ W1,
                                               const float* __restrict__ b1) {
    __shared__ __align__(16) float As[BK][BM];
    __shared__ __align__(16) float Bs[BK][BN];
    int m0 = blockIdx.y * BM, n0 = blockIdx.x * BN, tid = threadIdx.x;
    float acc[TM][TN] = {};
#pragma unroll 1
    for (int pass = 0; pass < 2; pass++) {
        const float* A = pass ? x : g_attn;
        const float* B = pass ? (W1 + (long)DIM * DIM) : W1;
        for (int k0 = 0; k0 < DIM; k0 += BK) {
            load_tile_A(A, DIM, m0, k0, tid, As);
            load_tile_B_nn(B, DIM, k0, n0, tid, Bs);
            __syncthreads();
            mma_tile(As, Bs, tid, acc);
            __syncthreads();
        }
    }
    store_tile(g_h, DIM, m0, n0, tid, acc, 1.0f, b1, true);
}

// out = h @ W2 + b2
__global__ __launch_bounds__(NTHR) void k_mlp2(const float* __restrict__ W2,
                                               const float* __restrict__ b2,
                                               float* __restrict__ out) {
    __shared__ __align__(16) float As[BK][BM];
    __shared__ __align__(16) float Bs[BK][BN];
    int m0 = blockIdx.y * BM, n0 = blockIdx.x * BN, tid = threadIdx.x;
    float acc[TM][TN] = {};
    for (int k0 = 0; k0 < DIM; k0 += BK) {
        load_tile_A(g_h, DIM, m0, k0, tid, As);
        load_tile_B_nn(W2, DIM, k0, n0, tid, Bs);
        __syncthreads();
        mma_tile(As, Bs, tid, acc);
        __syncthreads();
    }
    store_tile(out, DIM, m0, n0, tid, acc, 1.0f, b2, false);
}

// ---------------------------------------------------------------------------
// Launch
// ---------------------------------------------------------------------------

extern "C" void kernel_launch(void* const* d_in, const int* in_sizes, int n_in,
                              void* d_out, int out_size) {
    const float* x  = (const float*)d_in[0];
    const float* Wq = (const float*)d_in[1];
    const float* Wk = (const float*)d_in[2];
    const float* Wv = (const float*)d_in[3];
    const float* W1 = (const float*)d_in[4];
    const float* b1 = (const float*)d_in[5];
    const float* W2 = (const float*)d_in[6];
    const float* b2 = (const float*)d_in[7];
    float* out = (float*)d_out;

    dim3 thr(NTHR);

    // QKV projections: [8192,1024] x [1024,1024] x3
    k_qkv<<<dim3(DIM / BN, MTOT / BM, 3), thr>>>(x, Wq, Wk, Wv);

    // scores = q k^T * scale (lower-triangular blocks only)
    k_scores<<<dim3(SEQ / BN, SEQ / BM, BSZ), thr>>>();

    // causal softmax (also zeroes the masked upper triangle)
    k_softmax<<<dim3(BSZ * SEQ), thr>>>();

    // attn @ v with causal K-limit
    k_av<<<dim3(DIM / BN, SEQ / BM, BSZ), thr>>>();

    // MLP layer 1: concat([attn_out, x]) @ W1 + b1, relu
    k_mlp1<<<dim3(DIM / BN, MTOT / BM, 1), thr>>>(x, W1, b1);

    // MLP layer 2: h @ W2 + b2 -> output
    k_mlp2<<<dim3(DIM / BN, MTOT / BM, 1), thr>>>(W2, b2, out);
}

// round 3
// speedup vs baseline: 2.7544x; 2.7544x over previous
#include <cuda_runtime.h>
#include <cuda_bf16.h>
#include <cstdint>

#define BSZ 4
#define SEQ 2048
#define DIM 1024
#define MTOT (BSZ*SEQ)

// ---------------------------------------------------------------------------
// Static scratch. "Packed" layout: bf16 buffer where each row of K floats is
// stored as K/32 chunks of 128 bytes: [32 bf16 hi][32 bf16 lo].
// Row byte stride = K*4 (same as fp32 row).
// ---------------------------------------------------------------------------
__device__ __align__(128) char g_xpk   [(size_t)MTOT * DIM * 4];        // x packed
__device__ __align__(128) char g_wpk   [(size_t)3 * DIM * DIM * 4];     // WqT|WkT|WvT packed
__device__ __align__(128) char g_w1pk  [(size_t)DIM * 2 * DIM * 4];     // W1T packed (rows=out n, K=2048)
__device__ __align__(128) char g_w2pk  [(size_t)DIM * DIM * 4];         // W2T packed
__device__ __align__(128) char g_qkpk  [(size_t)2 * MTOT * DIM * 4];    // q | k packed
__device__ __align__(128) float g_v    [(size_t)MTOT * DIM];            // v fp32
__device__ __align__(128) char g_vtpk  [(size_t)BSZ * DIM * SEQ * 4];   // vT packed (rows=d, K=s)
__device__ __align__(128) float g_scores[(size_t)BSZ * SEQ * SEQ];      // fp32 scores
__device__ __align__(128) char g_ppk   [(size_t)BSZ * SEQ * SEQ * 4];   // probs packed
__device__ __align__(128) char g_apk   [(size_t)MTOT * DIM * 4];        // attn out packed
__device__ __align__(128) char g_hpk   [(size_t)MTOT * DIM * 4];        // mlp hidden packed

// ---------------------------------------------------------------------------
// Helpers
// ---------------------------------------------------------------------------
__device__ __forceinline__ uint32_t smem_u32(const void* p) {
    uint32_t a;
    asm("{ .reg .u64 t; cvta.to.shared.u64 t, %1; cvt.u32.u64 %0, t; }" : "=r"(a) : "l"(p));
    return a;
}
__device__ __forceinline__ uint32_t swz(uint32_t x) { return x ^ ((x >> 3) & 0x70); }

// packed pair: low16 = bf16(v0), high16 = bf16(v1)
__device__ __forceinline__ uint32_t bfpair(float v0, float v1) {
    uint32_t r;
    asm("cvt.rn.bf16x2.f32 %0, %1, %2;" : "=r"(r) : "f"(v1), "f"(v0));
    return r;
}
// residual pair for the lo plane given hi pair
__device__ __forceinline__ uint32_t bflo(float v0, float v1, uint32_t hi) {
    float h0 = __uint_as_float(hi << 16);
    float h1 = __uint_as_float(hi & 0xffff0000u);
    return bfpair(v0 - h0, v1 - h1);
}

__device__ __forceinline__ void ldsm4(uint32_t* r, uint32_t addr) {
    asm volatile("ldmatrix.sync.aligned.m8n8.x4.shared.b16 {%0,%1,%2,%3}, [%4];"
                 : "=r"(r[0]), "=r"(r[1]), "=r"(r[2]), "=r"(r[3]) : "r"(addr));
}
__device__ __forceinline__ void mma16816(float* d, const uint32_t* a, const uint32_t* b) {
    asm volatile(
        "mma.sync.aligned.m16n8k16.row.col.f32.bf16.bf16.f32 "
        "{%0,%1,%2,%3}, {%4,%5,%6,%7}, {%8,%9}, {%0,%1,%2,%3};"
        : "+f"(d[0]), "+f"(d[1]), "+f"(d[2]), "+f"(d[3])
        : "r"(a[0]), "r"(a[1]), "r"(a[2]), "r"(a[3]), "r"(b[0]), "r"(b[1]));
}

// ---------------------------------------------------------------------------
// Generic NT GEMM on packed operands.
// C[m][n] = scale * sum_k A[m][k]*B[n][k] (+bias)(relu)
// A/B packed hi|lo bf16; 3-term split MMA; fp32 or packed output.
// mode: 1=relu, 2=causal block skip, 4=causal k-limit, 8=packed output
// ---------------------------------------------------------------------------
#define ST 3
#define GEMM_SMEM (ST * 32768)

__global__ __launch_bounds__(256) void gemm_mma(
    const char* __restrict__ Ap, const char* __restrict__ Bp,
    long aRB, long bRB, long zsA, long zsB, int kc1,
    const char* __restrict__ Ap2, const char* __restrict__ Bp2,
    long aRB2, long bRB2, int kc2,
    void* Cout, long zsC, int ldc, long cRB,
    float scale, const float* __restrict__ bias, int mode)
{
    int m0 = blockIdx.y * 128, n0 = blockIdx.x * 128;
    if ((mode & 2) && n0 > m0) return;
    if (mode & 4) { int ke = (m0 + 128) >> 5; if (ke < kc1) kc1 = ke; }
    int z = blockIdx.z;
    Ap += (long)z * zsA;
    Bp += (long)z * zsB;
    char* Cb = (char*)Cout + (long)z * zsC;

    extern __shared__ char smem[];
    uint32_t sb = smem_u32(smem);
    int tid = threadIdx.x;
    int nch = kc1 + kc2;

    // copy roles: threads 0-127 -> A tile, 128-255 -> B tile
    int which = tid >> 7;
    int idx = tid & 127;
    int crow0 = idx >> 3;    // rows crow0 + 16*i
    int cseg = idx & 7;
    int base0 = which ? n0 : m0;

    auto issue = [&](int c) {
        const char* p; long rb; int cc = c;
        if (c < kc1) { p = which ? Bp : Ap;   rb = which ? bRB : aRB; }
        else         { p = which ? Bp2 : Ap2; rb = which ? bRB2 : aRB2; cc = c - kc1; }
        uint32_t tb = sb + (uint32_t)(c % ST) * 32768u + (uint32_t)which * 16384u;
        const char* gb = p + (long)cc * 128 + cseg * 16;
#pragma unroll
        for (int i = 0; i < 8; i++) {
            int row = crow0 + i * 16;
            const char* g = gb + (long)(base0 + row) * rb;
            uint32_t s = tb + swz((uint32_t)(row * 128 + cseg * 16));
            asm volatile("cp.async.cg.shared.global [%0], [%1], 16;" :: "r"(s), "l"(g));
        }
        asm volatile("cp.async.commit_group;" ::: "memory");
    };

    int wid = tid >> 5, lane = tid & 31;
    int wm = wid >> 2, wn = wid & 3;
    float acc[4][4][4] = {};

    int npro = nch < ST ? nch : ST;
    for (int c = 0; c < npro; c++) issue(c);

    // precomputed lane pieces
    uint32_t aRowLoc = (uint32_t)((wm * 64 + (lane & 15)) * 128 + ((lane >> 4) << 4));
    int bg = lane >> 3;
    uint32_t bRowLoc = (uint32_t)((wn * 32 + (lane & 7) + ((bg >> 1) << 3)) * 128 + ((bg & 1) << 4));

    for (int c = 0; c < nch; c++) {
        asm volatile("cp.async.wait_group 2;" ::: "memory");
        __syncthreads();
        uint32_t ta = sb + (uint32_t)(c % ST) * 32768u;
        uint32_t tb = ta + 16384u;
#pragma unroll
        for (int pass = 0; pass < 3; pass++) {
            int aoff = (pass == 2) ? 64 : 0;
            int boff = (pass == 1) ? 64 : 0;
#pragma unroll
            for (int s = 0; s < 2; s++) {
                int ko = s * 32;
                uint32_t af[4][4];
#pragma unroll
                for (int mt = 0; mt < 4; mt++)
                    ldsm4(af[mt], ta + swz(aRowLoc + mt * 16 * 128 + aoff + ko));
                uint32_t bf[2][4];
#pragma unroll
                for (int bt = 0; bt < 2; bt++)
                    ldsm4(bf[bt], tb + swz(bRowLoc + bt * 16 * 128 + boff + ko));
#pragma unroll
                for (int mt = 0; mt < 4; mt++)
#pragma unroll
                    for (int nt = 0; nt < 4; nt++)
                        mma16816(acc[mt][nt], af[mt], &bf[nt >> 1][(nt & 1) * 2]);
            }
        }
        __syncthreads();
        if (c + ST < nch) issue(c + ST);
    }

    // Epilogue
    int q = lane & 3;
    int r0 = m0 + wm * 64 + (lane >> 2);
    if (mode & 8) {
        int cw = (n0 + wn * 32) >> 5;
        char* cbase = Cb + (long)cw * 128;
#pragma unroll
        for (int mt = 0; mt < 4; mt++) {
#pragma unroll
            for (int half = 0; half < 2; half++) {
                long row = r0 + mt * 16 + half * 8;
                char* rp = cbase + row * cRB;
#pragma unroll
                for (int nt = 0; nt < 4; nt++) {
                    float v0 = acc[mt][nt][half * 2 + 0] * scale;
                    float v1 = acc[mt][nt][half * 2 + 1] * scale;
                    int col = n0 + wn * 32 + nt * 8 + q * 2;
                    if (bias) { v0 += bias[col]; v1 += bias[col + 1]; }
                    if (mode & 1) { v0 = fmaxf(v0, 0.f); v1 = fmaxf(v1, 0.f); }
                    uint32_t hi = bfpair(v0, v1);
                    uint32_t lo = bflo(v0, v1, hi);
                    int wb = (nt * 8 + q * 2) * 2;
                    *(uint32_t*)(rp + wb) = hi;
                    *(uint32_t*)(rp + wb + 64) = lo;
                }
            }
        }
    } else {
        float* Cf = (float*)Cb;
#pragma unroll
        for (int mt = 0; mt < 4; mt++) {
#pragma unroll
            for (int half = 0; half < 2; half++) {
                long row = r0 + mt * 16 + half * 8;
#pragma unroll
                for (int nt = 0; nt < 4; nt++) {
                    float v0 = acc[mt][nt][half * 2 + 0] * scale;
                    float v1 = acc[mt][nt][half * 2 + 1] * scale;
                    int col = n0 + wn * 32 + nt * 8 + q * 2;
                    if (bias) { v0 += bias[col]; v1 += bias[col + 1]; }
                    if (mode & 1) { v0 = fmaxf(v0, 0.f); v1 = fmaxf(v1, 0.f); }
                    float2 vv = make_float2(v0, v1);
                    *(float2*)(Cf + row * (long)ldc + col) = vv;
                }
            }
        }
    }
}

// ---------------------------------------------------------------------------
// Pack fp32 [rows][K] -> packed hi|lo (row length K, multiple of 32)
// ---------------------------------------------------------------------------
__global__ __launch_bounds__(256) void k_pack(const float* __restrict__ src,
                                              char* __restrict__ dst, int K) {
    long j0 = ((long)blockIdx.x * 256 + threadIdx.x) * 8;
    float4 f0 = *(const float4*)(src + j0);
    float4 f1 = *(const float4*)(src + j0 + 4);
    long row = j0 / K;
    int k0 = (int)(j0 - row * K);
    uint32_t h0 = bfpair(f0.x, f0.y), h1 = bfpair(f0.z, f0.w);
    uint32_t h2 = bfpair(f1.x, f1.y), h3 = bfpair(f1.z, f1.w);
    uint32_t l0 = bflo(f0.x, f0.y, h0), l1 = bflo(f0.z, f0.w, h1);
    uint32_t l2 = bflo(f1.x, f1.y, h2), l3 = bflo(f1.z, f1.w, h3);
    char* p = dst + row * (long)K * 4 + (k0 >> 5) * 128 + (k0 & 31) * 2;
    *(uint4*)p = make_uint4(h0, h1, h2, h3);
    *(uint4*)(p + 64) = make_uint4(l0, l1, l2, l3);
}

// ---------------------------------------------------------------------------
// Transpose + pack: in fp32 [R][C] -> packed rows=C, K=R (out[c][r]=in[r][c])
// ---------------------------------------------------------------------------
__global__ __launch_bounds__(256) void k_transpack(const float* __restrict__ in,
                                                   char* __restrict__ out,
                                                   int R, int C,
                                                   long inPlane, long outPlaneBytes) {
    in  += (long)blockIdx.z * inPlane;
    out += (long)blockIdx.z * outPlaneBytes;
    int c0 = blockIdx.x * 32, r0 = blockIdx.y * 32;
    __shared__ float t[32][33];
    int tx = threadIdx.x & 31, ty = threadIdx.x >> 5;
#pragma unroll
    for (int i = ty; i < 32; i += 8)
        t[i][tx] = in[(long)(r0 + i) * C + c0 + tx];
    __syncthreads();
    int i = threadIdx.x >> 3;        // output row (col of in)
    int g = (threadIdx.x & 7) * 4;   // k within 32-chunk
    float v0 = t[g + 0][i], v1 = t[g + 1][i], v2 = t[g + 2][i], v3 = t[g + 3][i];
    uint32_t h0 = bfpair(v0, v1), h1 = bfpair(v2, v3);
    uint32_t l0 = bflo(v0, v1, h0), l1 = bflo(v2, v3, h1);
    char* p = out + (long)(c0 + i) * ((long)R * 4) + (r0 >> 5) * 128 + g * 2;
    *(uint2*)p = make_uint2(h0, h1);
    *(uint2*)(p + 64) = make_uint2(l0, l1);
}

// ---------------------------------------------------------------------------
// Causal softmax: read fp32 scores row, write packed probs row
// ---------------------------------------------------------------------------
__global__ __launch_bounds__(256) void k_softmax() {
    long rowi = blockIdx.x;
    const float* p = g_scores + rowi * SEQ;
    char* dst = g_ppk + rowi * (SEQ * 4);
    int cnt = (int)(rowi & (SEQ - 1)) + 1;
    int tid = threadIdx.x;
    int j0 = tid * 8;
    __shared__ float red[256];

    float v[8];
    float4 f0 = *(const float4*)(p + j0);
    float4 f1 = *(const float4*)(p + j0 + 4);
    v[0]=f0.x; v[1]=f0.y; v[2]=f0.z; v[3]=f0.w;
    v[4]=f1.x; v[5]=f1.y; v[6]=f1.z; v[7]=f1.w;
    float m = -3.4e38f;
#pragma unroll
    for (int i = 0; i < 8; i++) {
        if (j0 + i >= cnt) v[i] = -3.4e38f;
        m = fmaxf(m, v[i]);
    }
    red[tid] = m;
    __syncthreads();
    for (int s = 128; s > 0; s >>= 1) {
        if (tid < s) red[tid] = fmaxf(red[tid], red[tid + s]);
        __syncthreads();
    }
    m = red[0];
    __syncthreads();
    float sum = 0.f;
#pragma unroll
    for (int i = 0; i < 8; i++) {
        v[i] = (j0 + i < cnt) ? __expf(v[i] - m) : 0.f;
        sum += v[i];
    }
    red[tid] = sum;
    __syncthreads();
    for (int s = 128; s > 0; s >>= 1) {
        if (tid < s) red[tid] += red[tid + s];
        __syncthreads();
    }
    float inv = 1.0f / red[0];
#pragma unroll
    for (int i = 0; i < 8; i++) v[i] *= inv;

    uint32_t h0 = bfpair(v[0], v[1]), h1 = bfpair(v[2], v[3]);
    uint32_t h2 = bfpair(v[4], v[5]), h3 = bfpair(v[6], v[7]);
    uint32_t l0 = bflo(v[0], v[1], h0), l1 = bflo(v[2], v[3], h1);
    uint32_t l2 = bflo(v[4], v[5], h2), l3 = bflo(v[6], v[7], h3);
    char* q = dst + (tid >> 2) * 128 + (tid & 3) * 16;
    *(uint4*)q = make_uint4(h0, h1, h2, h3);
    *(uint4*)(q + 64) = make_uint4(l0, l1, l2, l3);
}

// ---------------------------------------------------------------------------
// Launch
// ---------------------------------------------------------------------------
extern "C" void kernel_launch(void* const* d_in, const int* in_sizes, int n_in,
                              void* d_out, int out_size) {
    const float* x  = (const float*)d_in[0];
    const float* Wq = (const float*)d_in[1];
    const float* Wk = (const float*)d_in[2];
    const float* Wv = (const float*)d_in[3];
    const float* W1 = (const float*)d_in[4];
    const float* b1 = (const float*)d_in[5];
    const float* W2 = (const float*)d_in[6];
    const float* b2 = (const float*)d_in[7];
    float* out = (float*)d_out;

    cudaFuncSetAttribute(gemm_mma, cudaFuncAttributeMaxDynamicSharedMemorySize, GEMM_SMEM);

    void* p;
    cudaGetSymbolAddress(&p, g_xpk);   char* xpk  = (char*)p;
    cudaGetSymbolAddress(&p, g_wpk);   char* wpk  = (char*)p;
    cudaGetSymbolAddress(&p, g_w1pk);  char* w1pk = (char*)p;
    cudaGetSymbolAddress(&p, g_w2pk);  char* w2pk = (char*)p;
    cudaGetSymbolAddress(&p, g_qkpk);  char* qkpk = (char*)p;
    cudaGetSymbolAddress(&p, g_v);     float* v   = (float*)p;
    cudaGetSymbolAddress(&p, g_vtpk);  char* vtpk = (char*)p;
    cudaGetSymbolAddress(&p, g_scores);float* sc  = (float*)p;
    cudaGetSymbolAddress(&p, g_ppk);   char* ppk  = (char*)p;
    cudaGetSymbolAddress(&p, g_apk);   char* apk  = (char*)p;
    cudaGetSymbolAddress(&p, g_hpk);   char* hpk  = (char*)p;

    const long WPL = (long)DIM * DIM * 4;   // packed weight plane bytes

    // Pack x; transpose+pack weights
    k_pack<<<dim3((MTOT * DIM) / (8 * 256)), 256>>>(x, xpk, DIM);
    k_transpack<<<dim3(32, 32, 1), 256>>>(Wq, wpk + 0 * WPL, DIM, DIM, 0, 0);
    k_transpack<<<dim3(32, 32, 1), 256>>>(Wk, wpk + 1 * WPL, DIM, DIM, 0, 0);
    k_transpack<<<dim3(32, 32, 1), 256>>>(Wv, wpk + 2 * WPL, DIM, DIM, 0, 0);
    k_transpack<<<dim3(32, 64, 1), 256>>>(W1, w1pk, 2 * DIM, DIM, 0, 0);
    k_transpack<<<dim3(32, 32, 1), 256>>>(W2, w2pk, DIM, DIM, 0, 0);

    // q,k = x @ Wq/Wk  (packed out)
    gemm_mma<<<dim3(8, 64, 2), 256, GEMM_SMEM>>>(
        xpk, wpk, DIM * 4, DIM * 4, 0, WPL, 32,
        0, 0, 0, 0, 0,
        qkpk, (long)MTOT * DIM * 4, 0, DIM * 4,
        1.0f, 0, 8);
    // v = x @ Wv  (fp32 out)
    gemm_mma<<<dim3(8, 64, 1), 256, GEMM_SMEM>>>(
        xpk, wpk + 2 * WPL, DIM * 4, DIM * 4, 0, 0, 32,
        0, 0, 0, 0, 0,
        v, 0, DIM, 0,
        1.0f, 0, 0);
    // vT packed per batch: [2048,1024] -> rows=1024, K=2048
    k_transpack<<<dim3(32, 64, BSZ), 256>>>(v, vtpk, SEQ, DIM,
                                            (long)SEQ * DIM, (long)DIM * SEQ * 4);
    // scores = q k^T /32 (fp32 out, causal block skip)
    gemm_mma<<<dim3(16, 16, BSZ), 256, GEMM_SMEM>>>(
        qkpk, qkpk + (long)MTOT * DIM * 4,
        DIM * 4, DIM * 4, (long)SEQ * DIM * 4, (long)SEQ * DIM * 4, 32,
        0, 0, 0, 0, 0,
        sc, (long)SEQ * SEQ * 4, SEQ, 0,
        0.03125f, 0, 2);
    // softmax -> packed probs
    k_softmax<<<dim3(BSZ * SEQ), 256>>>();
    // attn = probs @ v (B = vT packed; causal k-limit; packed out)
    gemm_mma<<<dim3(8, 16, BSZ), 256, GEMM_SMEM>>>(
        ppk, vtpk, SEQ * 4, SEQ * 4, (long)SEQ * SEQ * 4, (long)DIM * SEQ * 4, 64,
        0, 0, 0, 0, 0,
        apk, (long)SEQ * DIM * 4, 0, DIM * 4,
        1.0f, 0, 4 | 8);
    // h = relu([attn|x] @ W1 + b1) (two K segments; packed out)
    gemm_mma<<<dim3(8, 64, 1), 256, GEMM_SMEM>>>(
        apk, w1pk, DIM * 4, 2 * DIM * 4, 0, 0, 32,
        xpk, w1pk + DIM * 4, DIM * 4, 2 * DIM * 4, 32,
        hpk, 0, 0, DIM * 4,
        1.0f, b1, 1 | 8);
    // out = h @ W2 + b2 (fp32)
    gemm_mma<<<dim3(8, 64, 1), 256, GEMM_SMEM>>>(
        hpk, w2pk, DIM * 4, DIM * 4, 0, 0, 32,
        0, 0, 0, 0, 0,
        out, 0, DIM, 0,
        1.0f, b2, 0);
}